// round 14
// baseline (speedup 1.0000x reference)
#include <cuda_runtime.h>
#include <cuda_bf16.h>
#include <cuda_fp8.h>
#include <math.h>
#include <stdint.h>

// ---------------------------------------------------------------- shapes
constexpr int Bn = 16, Tn = 512, Hn = 512, Vn = 4096, Ln = 64, Jn = 66;
constexpr int Mn = Bn * Tn;
constexpr int Smax = 2 * Ln + 1;
constexpr float NEGF = -1e30f;
constexpr float LOG2E = 1.4426950408889634f;
constexpr float LN2 = 0.6931471805599453f;
constexpr float WSCALE = 16.0f;
constexpr float INV_WSCALE = 1.0f / 16.0f;

// ---------------------------------------------------------------- scratch
__device__ uint8_t g_A8[(size_t)Mn * Hn];
__device__ uint8_t g_B8[(size_t)Vn * Hn];
__device__ float2  g_part[(size_t)Mn * 32];   // 1 partial per CTA per row
__device__ float   g_gath[(size_t)Mn * Jn];
__device__ int     g_rep[Bn * Jn];
__device__ float   g_ll[Bn];
__device__ int     g_ctr;

// ---------------------------------------------------------------- helpers
__device__ __forceinline__ uint32_t smem_u32(const void* p) {
    uint32_t a;
    asm("{ .reg .u64 t; cvta.to.shared.u64 t, %1; cvt.u32.u64 %0, t; }" : "=r"(a) : "l"(p));
    return a;
}
__device__ __forceinline__ void ldm_x4(uint32_t* r, uint32_t addr) {
    asm volatile("ldmatrix.sync.aligned.m8n8.x4.shared.b16 {%0,%1,%2,%3}, [%4];"
                 : "=r"(r[0]), "=r"(r[1]), "=r"(r[2]), "=r"(r[3]) : "r"(addr));
}
__device__ __forceinline__ void ldm_x2(uint32_t* r, uint32_t addr) {
    asm volatile("ldmatrix.sync.aligned.m8n8.x2.shared.b16 {%0,%1}, [%2];"
                 : "=r"(r[0]), "=r"(r[1]) : "r"(addr));
}
__device__ __forceinline__ void mma_fp8(float* d, const uint32_t* a, const uint32_t* b) {
    asm volatile("mma.sync.aligned.m16n8k32.row.col.f32.e4m3.e4m3.f32 "
                 "{%0,%1,%2,%3}, {%4,%5,%6,%7}, {%8,%9}, {%0,%1,%2,%3};"
                 : "+f"(d[0]), "+f"(d[1]), "+f"(d[2]), "+f"(d[3])
                 : "r"(a[0]), "r"(a[1]), "r"(a[2]), "r"(a[3]), "r"(b[0]), "r"(b[1]));
}
__device__ __forceinline__ float ex2(float x) {
    float r; asm("ex2.approx.ftz.f32 %0, %1;" : "=f"(r) : "f"(x)); return r;
}
__device__ __forceinline__ float lg2(float x) {
    float r; asm("lg2.approx.f32 %0, %1;" : "=f"(r) : "f"(x)); return r;
}
__device__ __forceinline__ uint16_t f2_to_e4m3x2(float x, float y) {
    return (uint16_t)__nv_cvt_float2_to_fp8x2(make_float2(x, y), __NV_SATFINITE, __NV_E4M3);
}
#define CP_ASYNC16(dst, src) \
    asm volatile("cp.async.cg.shared.global [%0], [%1], 16;" :: "r"(dst), "l"(src) : "memory")
#define CP_COMMIT() asm volatile("cp.async.commit_group;" ::: "memory")
#define CP_WAIT2()  asm volatile("cp.async.wait_group 2;" ::: "memory")

// ---------------------------------------------------------------- fused preprocessing
__global__ __launch_bounds__(256) void prep_kernel(const float* __restrict__ hs,
                                                   const float* __restrict__ W,
                                                   const int* __restrict__ ys) {
    const int bid = blockIdx.x, tid = threadIdx.x;
    if (bid < 4096) {
        size_t i = (size_t)bid * 256 + tid;
        float4 v = ((const float4*)hs)[i];
        uint32_t u = (uint32_t)f2_to_e4m3x2(v.x, v.y) | ((uint32_t)f2_to_e4m3x2(v.z, v.w) << 16);
        ((uint32_t*)g_A8)[i] = u;
    } else if (bid < 6144) {
        __shared__ float tile[32][33];
        const int vb = bid - 4096;
        const int v0 = (vb & 127) * 32, k0 = (vb >> 7) * 32;
        const int tx = tid & 31, ty = tid >> 5;
#pragma unroll
        for (int j = 0; j < 4; j++)
            tile[ty + 8 * j][tx] = W[(size_t)(k0 + ty + 8 * j) * Vn + v0 + tx];
        __syncthreads();
#pragma unroll
        for (int j = 0; j < 4; j++) {
            int vl = ty + 8 * j;
            __nv_fp8_e4m3 q(tile[tx][vl] * WSCALE);
            g_B8[(size_t)(v0 + vl) * Hn + k0 + tx] = *(uint8_t*)&q;
        }
    } else if (bid < 6160) {
        const int b = bid - 6144;
        const int j = tid;
        if (j < 65) {
            const int vid = (j == 0) ? 0 : ys[b * Ln + j - 1];
            int r = j;
            for (int q = 0; q < j; q++) {
                const int vq = (q == 0) ? 0 : ys[b * Ln + q - 1];
                if (vq == vid) { r = q; break; }
            }
            g_rep[b * Jn + j] = r;
        }
    } else {
        if (tid == 0) g_ctr = 0;
    }
}

// ---------------------------------------------------------------- FP8 MMA GEMM (R11 mainloop + reduced partials)
constexpr int STAGES = 4;
constexpr int STAGE_BYTES = 16384;
constexpr int GEMM_SMEM = STAGES * STAGE_BYTES;

__global__ __launch_bounds__(256, 2) void gemm_mma_kernel(const int* __restrict__ ys,
                                                          const float* __restrict__ bias) {
    extern __shared__ __align__(1024) char sm[];
    __shared__ float sbias[128];
    __shared__ int stable[128];
    __shared__ float2 sred[4][128];

    const int tid = threadIdx.x, w = tid >> 5, lane = tid & 31;
    const int bn = blockIdx.x * 128, bm = blockIdx.y * 128;
    const int b = blockIdx.y >> 2;

    if (tid < 128) { sbias[tid] = bias[bn + tid]; stable[tid] = -1; }
    __syncthreads();
    if (tid == 0) {
        for (int j = 0; j < 65; j++) {
            const int vid = (j == 0) ? 0 : ys[b * Ln + j - 1];
            const int idx = vid - bn;
            if (idx >= 0 && idx < 128 && stable[idx] < 0) stable[idx] = j;
        }
    }

    const int row = tid >> 1, kp = tid & 1;
    const uint8_t* gA = g_A8 + (size_t)(bm + row) * Hn + kp * 16;
    const uint8_t* gB = g_B8 + (size_t)(bn + row) * Hn + kp * 16;
    const uint32_t smb = smem_u32(sm);
    const uint32_t stsA = smb + (uint32_t)(kp * 2) * 2048 + (uint32_t)row * 16;

    const int wm = w >> 2, wn = w & 3;
    const uint32_t aBase = smb + (uint32_t)(wm * 64 + (lane & 15)) * 16 + (uint32_t)(lane >> 4) * 2048;
    const uint32_t bBase = smb + 8192 + (uint32_t)(wn * 32 + (lane & 7)) * 16 + (uint32_t)((lane >> 3) & 1) * 2048;

    float acc[4][4][4];
#pragma unroll
    for (int mi = 0; mi < 4; mi++)
#pragma unroll
        for (int ni = 0; ni < 4; ni++)
#pragma unroll
            for (int e = 0; e < 4; e++) acc[mi][ni][e] = 0.f;

    const int NC = Hn / 64;

#define ISSUE_STAGE(slot, c)                                                   \
    do {                                                                       \
        const uint32_t so = (uint32_t)(slot) * STAGE_BYTES;                    \
        _Pragma("unroll")                                                      \
        for (int i = 0; i < 2; i++) {                                          \
            CP_ASYNC16(stsA + so + i * 2048, gA + (c) * 64 + i * 32);          \
            CP_ASYNC16(stsA + so + 8192 + i * 2048, gB + (c) * 64 + i * 32);   \
        }                                                                      \
    } while (0)

#pragma unroll
    for (int c = 0; c < 3; c++) { ISSUE_STAGE(c, c); CP_COMMIT(); }

    for (int c = 0; c < NC; c++) {
        CP_WAIT2();
        __syncthreads();
        if (c + 3 < NC) ISSUE_STAGE((c + 3) & (STAGES - 1), c + 3);
        CP_COMMIT();

        const uint32_t so = (uint32_t)(c & (STAGES - 1)) * STAGE_BYTES;
#pragma unroll
        for (int kk = 0; kk < 2; kk++) {
            uint32_t aF[4][4], bF[4][2];
#pragma unroll
            for (int mi = 0; mi < 4; mi++)
                ldm_x4(aF[mi], aBase + so + kk * 4096 + mi * 256);
#pragma unroll
            for (int ni = 0; ni < 4; ni++)
                ldm_x2(bF[ni], bBase + so + kk * 4096 + ni * 128);
#pragma unroll
            for (int mi = 0; mi < 4; mi++)
#pragma unroll
                for (int ni = 0; ni < 4; ni++)
                    mma_fp8(acc[mi][ni], aF[mi], bF[ni]);
        }
    }

    // ---- fused epilogue: rescale + bias, per-warp partials -> smem, label gather
    const int tq = lane >> 2, lq = lane & 3;
#pragma unroll
    for (int mi = 0; mi < 4; mi++) {
#pragma unroll
        for (int h = 0; h < 2; h++) {
            const int rloc = wm * 64 + mi * 16 + h * 8 + tq;
            const size_t grow = (size_t)(bm + rloc);
            float v[8];
            float mx = -3.4e38f;
#pragma unroll
            for (int ni = 0; ni < 4; ni++)
#pragma unroll
                for (int e = 0; e < 2; e++) {
                    float f = acc[mi][ni][h * 2 + e] * INV_WSCALE + sbias[wn * 32 + ni * 8 + lq * 2 + e];
                    v[ni * 2 + e] = f;
                    mx = fmaxf(mx, f);
                }
            float sum = 0.f;
#pragma unroll
            for (int i = 0; i < 8; i++) sum += __expf(v[i] - mx);
#pragma unroll
            for (int o = 1; o <= 2; o <<= 1) {
                float mo = __shfl_xor_sync(0xffffffffu, mx, o);
                float so2 = __shfl_xor_sync(0xffffffffu, sum, o);
                float m2 = fmaxf(mx, mo);
                sum = sum * __expf(mx - m2) + so2 * __expf(mo - m2);
                mx = m2;
            }
            if (lq == 0) sred[wn][rloc] = make_float2(mx, sum);
#pragma unroll
            for (int ni = 0; ni < 4; ni++)
#pragma unroll
                for (int e = 0; e < 2; e++) {
                    const int cidx = wn * 32 + ni * 8 + lq * 2 + e;
                    const int slot = stable[cidx];
                    if (slot >= 0) g_gath[grow * Jn + slot] = v[ni * 2 + e];
                }
        }
    }
    // ---- cross-warp reduce: 4 partials -> 1 per row
    __syncthreads();
    if (tid < 128) {
        float2 p0 = sred[0][tid], p1 = sred[1][tid], p2 = sred[2][tid], p3 = sred[3][tid];
        float m = fmaxf(fmaxf(p0.x, p1.x), fmaxf(p2.x, p3.x));
        float s = p0.y * __expf(p0.x - m) + p1.y * __expf(p1.x - m)
                + p2.y * __expf(p2.x - m) + p3.y * __expf(p3.x - m);
        g_part[(size_t)(bm + tid) * 32 + blockIdx.x] = make_float2(m, s);
    }
}

// ---------------------------------------------------------------- CTC DP with inline LSE + emit staging
// Staging: each warp handles rows t = w, w+5, ...; lane reads 1 of 32 partials,
// shfl-reduce to lse, then writes the 65 emissions (log2 domain) to smem.
__global__ __launch_bounds__(160) void ctc_dp_kernel(const int* __restrict__ ys,
                                                     const int* __restrict__ hlen,
                                                     const int* __restrict__ ylen,
                                                     float* __restrict__ out) {
    extern __shared__ float sem[];   // [Tn][Jn] log2-domain emissions
    __shared__ float sbuf[2][20];
    __shared__ float sal[Smax + 12];
    __shared__ int srep[Jn];

    const int b = blockIdx.x, tid = threadIdx.x;
    const int w = tid >> 5, lane = tid & 31;
    const int s = w * 28 + lane - 4;
    const int inlen = hlen[b];

    if (tid < 65) srep[tid] = g_rep[b * Jn + tid];
    __syncthreads();

    // staging: per-row LSE from g_part + gather adjust
    for (int t = w; t < inlen; t += 5) {
        const size_t rowg = (size_t)(b * Tn + t);
        float2 p = g_part[rowg * 32 + lane];
        float m = p.x;
#pragma unroll
        for (int o = 16; o > 0; o >>= 1) m = fmaxf(m, __shfl_xor_sync(0xffffffffu, m, o));
        float su = p.y * __expf(p.x - m);
#pragma unroll
        for (int o = 16; o > 0; o >>= 1) su += __shfl_xor_sync(0xffffffffu, su, o);
        const float lse = m + __logf(su);
        const float* gr = g_gath + rowg * Jn;
        float* dr = sem + t * Jn;
#pragma unroll
        for (int j = lane; j < 65; j += 32)
            dr[j] = (gr[srep[j]] - lse) * LOG2E;
    }

    int jj = 0;
    bool skipv = false;
    if (s >= 0 && s < Smax && (s & 1)) {
        const int li = (s - 1) >> 1;
        jj = li + 1;
        const int lab = ys[b * Ln + li];
        if (s >= 3) skipv = (lab != 0) && (lab != ys[b * Ln + li - 1]);
    }
    __syncthreads();

    float a = (s == 0) ? sem[0] : (s == 1) ? sem[1] : NEGF;
    int pb = 0;
    if (lane >= 28) sbuf[0][w * 4 + lane - 28] = a;
    __syncthreads();

    for (int t = 1; t < inlen; t += 2) {
        if (lane < 4) a = (w > 0) ? sbuf[pb][(w - 1) * 4 + lane] : NEGF;
        {
            const float e = sem[t * Jn + jj];
            const float up1 = __shfl_up_sync(0xffffffffu, a, 1);
            const float up2 = __shfl_up_sync(0xffffffffu, a, 2);
            const float am2 = skipv ? up2 : NEGF;
            const float m = fmaxf(fmaxf(a, up1), am2);
            a = m + lg2(ex2(a - m) + ex2(up1 - m) + ex2(am2 - m)) + e;
        }
        if (t + 1 < inlen) {
            const float e = sem[(t + 1) * Jn + jj];
            const float up1 = __shfl_up_sync(0xffffffffu, a, 1);
            const float up2 = __shfl_up_sync(0xffffffffu, a, 2);
            const float am2 = skipv ? up2 : NEGF;
            const float m = fmaxf(fmaxf(a, up1), am2);
            a = m + lg2(ex2(a - m) + ex2(up1 - m) + ex2(am2 - m)) + e;
        }
        pb ^= 1;
        if (lane >= 28) sbuf[pb][w * 4 + lane - 28] = a;
        __syncthreads();
    }

    if (lane >= 4 && s < Smax) sal[s] = a;
    __syncthreads();
    if (tid == 0) {
        const int s2 = 2 * ylen[b];
        const float x = sal[s2], y = sal[s2 - 1];
        const float m = fmaxf(x, y), d = fminf(x, y) - m;
        g_ll[b] = -(m + lg2(1.f + ex2(d))) * LN2;
        __threadfence();
        const int done = atomicAdd(&g_ctr, 1);
        if (done == Bn - 1) {
            float acc = 0.f;
#pragma unroll
            for (int i = 0; i < Bn; i++) acc += g_ll[i];
            out[0] = acc / (float)Bn;
        }
    }
}

// ----------------------------------------------------------------
extern "C" void kernel_launch(void* const* d_in, const int* in_sizes, int n_in,
                              void* d_out, int out_size) {
    const float* hs   = (const float*)d_in[0];
    const int*   hlen = (const int*)d_in[1];
    const int*   ys   = (const int*)d_in[2];
    const int*   ylen = (const int*)d_in[3];
    const float* Wm   = (const float*)d_in[4];
    const float* bias = (const float*)d_in[5];
    float* out = (float*)d_out;

    static bool attrs_set = false;
    if (!attrs_set) {
        cudaFuncSetAttribute(gemm_mma_kernel, cudaFuncAttributeMaxDynamicSharedMemorySize, GEMM_SMEM);
        cudaFuncSetAttribute(ctc_dp_kernel, cudaFuncAttributeMaxDynamicSharedMemorySize, Tn * Jn * 4);
        attrs_set = true;
    }

    prep_kernel<<<6161, 256>>>(hs, Wm, ys);
    gemm_mma_kernel<<<dim3(Vn / 128, Mn / 128), 256, GEMM_SMEM>>>(ys, bias);
    ctc_dp_kernel<<<Bn, 160, Tn * Jn * 4>>>(ys, hlen, ylen, out);
}

// round 15
// speedup vs baseline: 1.3606x; 1.3606x over previous
#include <cuda_runtime.h>
#include <cuda_bf16.h>
#include <cuda_fp8.h>
#include <math.h>
#include <stdint.h>

// ---------------------------------------------------------------- shapes
constexpr int Bn = 16, Tn = 512, Hn = 512, Vn = 4096, Ln = 64, Jn = 66;
constexpr int Mn = Bn * Tn;
constexpr int Smax = 2 * Ln + 1;
constexpr float NEGF = -1e30f;
constexpr float LOG2E = 1.4426950408889634f;
constexpr float LN2 = 0.6931471805599453f;
constexpr float WSCALE = 16.0f;
constexpr float INV_WSCALE = 1.0f / 16.0f;

// ---------------------------------------------------------------- scratch
__device__ uint8_t g_A8[(size_t)Mn * Hn];
__device__ uint8_t g_B8[(size_t)Vn * Hn];
__device__ float2  g_part[(size_t)Mn * 32];   // 1 partial per CTA per row (2 MB)
__device__ float   g_gath[(size_t)Mn * Jn];
__device__ float   g_emit[(size_t)Mn * Jn];
__device__ int     g_rep[Bn * Jn];
__device__ float   g_ll[Bn];
__device__ int     g_ctr;

// ---------------------------------------------------------------- helpers
__device__ __forceinline__ uint32_t smem_u32(const void* p) {
    uint32_t a;
    asm("{ .reg .u64 t; cvta.to.shared.u64 t, %1; cvt.u32.u64 %0, t; }" : "=r"(a) : "l"(p));
    return a;
}
__device__ __forceinline__ void ldm_x4(uint32_t* r, uint32_t addr) {
    asm volatile("ldmatrix.sync.aligned.m8n8.x4.shared.b16 {%0,%1,%2,%3}, [%4];"
                 : "=r"(r[0]), "=r"(r[1]), "=r"(r[2]), "=r"(r[3]) : "r"(addr));
}
__device__ __forceinline__ void ldm_x2(uint32_t* r, uint32_t addr) {
    asm volatile("ldmatrix.sync.aligned.m8n8.x2.shared.b16 {%0,%1}, [%2];"
                 : "=r"(r[0]), "=r"(r[1]) : "r"(addr));
}
__device__ __forceinline__ void mma_fp8(float* d, const uint32_t* a, const uint32_t* b) {
    asm volatile("mma.sync.aligned.m16n8k32.row.col.f32.e4m3.e4m3.f32 "
                 "{%0,%1,%2,%3}, {%4,%5,%6,%7}, {%8,%9}, {%0,%1,%2,%3};"
                 : "+f"(d[0]), "+f"(d[1]), "+f"(d[2]), "+f"(d[3])
                 : "r"(a[0]), "r"(a[1]), "r"(a[2]), "r"(a[3]), "r"(b[0]), "r"(b[1]));
}
__device__ __forceinline__ float ex2(float x) {
    float r; asm("ex2.approx.ftz.f32 %0, %1;" : "=f"(r) : "f"(x)); return r;
}
__device__ __forceinline__ float lg2(float x) {
    float r; asm("lg2.approx.f32 %0, %1;" : "=f"(r) : "f"(x)); return r;
}
__device__ __forceinline__ uint16_t f2_to_e4m3x2(float x, float y) {
    return (uint16_t)__nv_cvt_float2_to_fp8x2(make_float2(x, y), __NV_SATFINITE, __NV_E4M3);
}
#define CP_ASYNC16(dst, src) \
    asm volatile("cp.async.cg.shared.global [%0], [%1], 16;" :: "r"(dst), "l"(src) : "memory")
#define CP_COMMIT() asm volatile("cp.async.commit_group;" ::: "memory")
#define CP_WAIT2()  asm volatile("cp.async.wait_group 2;" ::: "memory")

// ---------------------------------------------------------------- fused preprocessing
__global__ __launch_bounds__(256) void prep_kernel(const float* __restrict__ hs,
                                                   const float* __restrict__ W,
                                                   const int* __restrict__ ys) {
    const int bid = blockIdx.x, tid = threadIdx.x;
    if (bid < 4096) {
        size_t i = (size_t)bid * 256 + tid;
        float4 v = ((const float4*)hs)[i];
        uint32_t u = (uint32_t)f2_to_e4m3x2(v.x, v.y) | ((uint32_t)f2_to_e4m3x2(v.z, v.w) << 16);
        ((uint32_t*)g_A8)[i] = u;
    } else if (bid < 6144) {
        __shared__ float tile[32][33];
        const int vb = bid - 4096;
        const int v0 = (vb & 127) * 32, k0 = (vb >> 7) * 32;
        const int tx = tid & 31, ty = tid >> 5;
#pragma unroll
        for (int j = 0; j < 4; j++)
            tile[ty + 8 * j][tx] = W[(size_t)(k0 + ty + 8 * j) * Vn + v0 + tx];
        __syncthreads();
#pragma unroll
        for (int j = 0; j < 4; j++) {
            int vl = ty + 8 * j;
            __nv_fp8_e4m3 q(tile[tx][vl] * WSCALE);
            g_B8[(size_t)(v0 + vl) * Hn + k0 + tx] = *(uint8_t*)&q;
        }
    } else if (bid < 6160) {
        const int b = bid - 6144;
        const int j = tid;
        if (j < 65) {
            const int vid = (j == 0) ? 0 : ys[b * Ln + j - 1];
            int r = j;
            for (int q = 0; q < j; q++) {
                const int vq = (q == 0) ? 0 : ys[b * Ln + q - 1];
                if (vq == vid) { r = q; break; }
            }
            g_rep[b * Jn + j] = r;
        }
    } else {
        if (tid == 0) g_ctr = 0;
    }
}

// ---------------------------------------------------------------- FP8 MMA GEMM (R11 mainloop) + partial reduce
constexpr int STAGES = 4;
constexpr int STAGE_BYTES = 16384;
constexpr int GEMM_SMEM = STAGES * STAGE_BYTES;

__global__ __launch_bounds__(256, 2) void gemm_mma_kernel(const int* __restrict__ ys,
                                                          const float* __restrict__ bias) {
    extern __shared__ __align__(1024) char sm[];
    __shared__ float sbias[128];
    __shared__ int stable[128];
    __shared__ float2 sred[4][128];

    const int tid = threadIdx.x, w = tid >> 5, lane = tid & 31;
    const int bn = blockIdx.x * 128, bm = blockIdx.y * 128;
    const int b = blockIdx.y >> 2;

    if (tid < 128) { sbias[tid] = bias[bn + tid]; stable[tid] = -1; }
    __syncthreads();
    if (tid == 0) {
        for (int j = 0; j < 65; j++) {
            const int vid = (j == 0) ? 0 : ys[b * Ln + j - 1];
            const int idx = vid - bn;
            if (idx >= 0 && idx < 128 && stable[idx] < 0) stable[idx] = j;
        }
    }

    const int row = tid >> 1, kp = tid & 1;
    const uint8_t* gA = g_A8 + (size_t)(bm + row) * Hn + kp * 16;
    const uint8_t* gB = g_B8 + (size_t)(bn + row) * Hn + kp * 16;
    const uint32_t smb = smem_u32(sm);
    const uint32_t stsA = smb + (uint32_t)(kp * 2) * 2048 + (uint32_t)row * 16;

    const int wm = w >> 2, wn = w & 3;
    const uint32_t aBase = smb + (uint32_t)(wm * 64 + (lane & 15)) * 16 + (uint32_t)(lane >> 4) * 2048;
    const uint32_t bBase = smb + 8192 + (uint32_t)(wn * 32 + (lane & 7)) * 16 + (uint32_t)((lane >> 3) & 1) * 2048;

    float acc[4][4][4];
#pragma unroll
    for (int mi = 0; mi < 4; mi++)
#pragma unroll
        for (int ni = 0; ni < 4; ni++)
#pragma unroll
            for (int e = 0; e < 4; e++) acc[mi][ni][e] = 0.f;

    const int NC = Hn / 64;

#define ISSUE_STAGE(slot, c)                                                   \
    do {                                                                       \
        const uint32_t so = (uint32_t)(slot) * STAGE_BYTES;                    \
        _Pragma("unroll")                                                      \
        for (int i = 0; i < 2; i++) {                                          \
            CP_ASYNC16(stsA + so + i * 2048, gA + (c) * 64 + i * 32);          \
            CP_ASYNC16(stsA + so + 8192 + i * 2048, gB + (c) * 64 + i * 32);   \
        }                                                                      \
    } while (0)

#pragma unroll
    for (int c = 0; c < 3; c++) { ISSUE_STAGE(c, c); CP_COMMIT(); }

    for (int c = 0; c < NC; c++) {
        CP_WAIT2();
        __syncthreads();
        if (c + 3 < NC) ISSUE_STAGE((c + 3) & (STAGES - 1), c + 3);
        CP_COMMIT();

        const uint32_t so = (uint32_t)(c & (STAGES - 1)) * STAGE_BYTES;
#pragma unroll
        for (int kk = 0; kk < 2; kk++) {
            uint32_t aF[4][4], bF[4][2];
#pragma unroll
            for (int mi = 0; mi < 4; mi++)
                ldm_x4(aF[mi], aBase + so + kk * 4096 + mi * 256);
#pragma unroll
            for (int ni = 0; ni < 4; ni++)
                ldm_x2(bF[ni], bBase + so + kk * 4096 + ni * 128);
#pragma unroll
            for (int mi = 0; mi < 4; mi++)
#pragma unroll
                for (int ni = 0; ni < 4; ni++)
                    mma_fp8(acc[mi][ni], aF[mi], bF[ni]);
        }
    }

    // ---- fused epilogue: rescale + bias, per-warp partials -> smem, label gather
    const int tq = lane >> 2, lq = lane & 3;
#pragma unroll
    for (int mi = 0; mi < 4; mi++) {
#pragma unroll
        for (int h = 0; h < 2; h++) {
            const int rloc = wm * 64 + mi * 16 + h * 8 + tq;
            const size_t grow = (size_t)(bm + rloc);
            float v[8];
            float mx = -3.4e38f;
#pragma unroll
            for (int ni = 0; ni < 4; ni++)
#pragma unroll
                for (int e = 0; e < 2; e++) {
                    float f = acc[mi][ni][h * 2 + e] * INV_WSCALE + sbias[wn * 32 + ni * 8 + lq * 2 + e];
                    v[ni * 2 + e] = f;
                    mx = fmaxf(mx, f);
                }
            float sum = 0.f;
#pragma unroll
            for (int i = 0; i < 8; i++) sum += __expf(v[i] - mx);
#pragma unroll
            for (int o = 1; o <= 2; o <<= 1) {
                float mo = __shfl_xor_sync(0xffffffffu, mx, o);
                float so2 = __shfl_xor_sync(0xffffffffu, sum, o);
                float m2 = fmaxf(mx, mo);
                sum = sum * __expf(mx - m2) + so2 * __expf(mo - m2);
                mx = m2;
            }
            if (lq == 0) sred[wn][rloc] = make_float2(mx, sum);
#pragma unroll
            for (int ni = 0; ni < 4; ni++)
#pragma unroll
                for (int e = 0; e < 2; e++) {
                    const int cidx = wn * 32 + ni * 8 + lq * 2 + e;
                    const int slot = stable[cidx];
                    if (slot >= 0) g_gath[grow * Jn + slot] = v[ni * 2 + e];
                }
        }
    }
    // ---- cross-warp reduce: 4 partials -> 1 per row
    __syncthreads();
    if (tid < 128) {
        float2 p0 = sred[0][tid], p1 = sred[1][tid], p2 = sred[2][tid], p3 = sred[3][tid];
        float m = fmaxf(fmaxf(p0.x, p1.x), fmaxf(p2.x, p3.x));
        float s = p0.y * __expf(p0.x - m) + p1.y * __expf(p1.x - m)
                + p2.y * __expf(p2.x - m) + p3.y * __expf(p3.x - m);
        g_part[(size_t)(bm + tid) * 32 + blockIdx.x] = make_float2(m, s);
    }
}

// ---------------------------------------------------------------- LSE reduce (32 partials/row) + emit
__global__ __launch_bounds__(256) void lse_emit_kernel() {
    const int warp = threadIdx.x >> 5, lane = threadIdx.x & 31;
    const size_t row = (size_t)blockIdx.x * 8 + warp;
    const int b = (int)(row >> 9);
    float2 p = g_part[row * 32 + lane];
    float m = p.x;
#pragma unroll
    for (int o = 16; o > 0; o >>= 1) m = fmaxf(m, __shfl_xor_sync(0xffffffffu, m, o));
    float s = p.y * __expf(p.x - m);
#pragma unroll
    for (int o = 16; o > 0; o >>= 1) s += __shfl_xor_sync(0xffffffffu, s, o);
    const float lse = m + __logf(s);
#pragma unroll
    for (int j = lane; j < 65; j += 32)
        g_emit[row * Jn + j] = (g_gath[row * Jn + g_rep[b * Jn + j]] - lse) * LOG2E;
}

// ---------------------------------------------------------------- CTC DP: halo-4 wavefront (R11/R6 exact)
__global__ __launch_bounds__(160) void ctc_dp_kernel(const int* __restrict__ ys,
                                                     const int* __restrict__ hlen,
                                                     const int* __restrict__ ylen,
                                                     float* __restrict__ out) {
    extern __shared__ float sem[];
    __shared__ float sbuf[2][20];
    __shared__ float sal[Smax + 12];

    const int b = blockIdx.x, tid = threadIdx.x;
    const int w = tid >> 5, lane = tid & 31;
    const int s = w * 28 + lane - 4;
    const int inlen = hlen[b];

    {
        const float2* src = (const float2*)(g_emit + (size_t)b * Tn * Jn);
        float2* dst = (float2*)sem;
        const int n2 = inlen * (Jn / 2);
        for (int i = tid; i < n2; i += 160) dst[i] = src[i];
    }

    int jj = 0;
    bool skipv = false;
    if (s >= 0 && s < Smax && (s & 1)) {
        const int li = (s - 1) >> 1;
        jj = li + 1;
        const int lab = ys[b * Ln + li];
        if (s >= 3) skipv = (lab != 0) && (lab != ys[b * Ln + li - 1]);
    }
    __syncthreads();

    float a = (s == 0) ? sem[0] : (s == 1) ? sem[1] : NEGF;
    int pb = 0;
    if (lane >= 28) sbuf[0][w * 4 + lane - 28] = a;
    __syncthreads();

    for (int t = 1; t < inlen; t += 2) {
        if (lane < 4) a = (w > 0) ? sbuf[pb][(w - 1) * 4 + lane] : NEGF;
        {
            const float e = sem[t * Jn + jj];
            const float up1 = __shfl_up_sync(0xffffffffu, a, 1);
            const float up2 = __shfl_up_sync(0xffffffffu, a, 2);
            const float am2 = skipv ? up2 : NEGF;
            const float m = fmaxf(fmaxf(a, up1), am2);
            a = m + lg2(ex2(a - m) + ex2(up1 - m) + ex2(am2 - m)) + e;
        }
        if (t + 1 < inlen) {
            const float e = sem[(t + 1) * Jn + jj];
            const float up1 = __shfl_up_sync(0xffffffffu, a, 1);
            const float up2 = __shfl_up_sync(0xffffffffu, a, 2);
            const float am2 = skipv ? up2 : NEGF;
            const float m = fmaxf(fmaxf(a, up1), am2);
            a = m + lg2(ex2(a - m) + ex2(up1 - m) + ex2(am2 - m)) + e;
        }
        pb ^= 1;
        if (lane >= 28) sbuf[pb][w * 4 + lane - 28] = a;
        __syncthreads();
    }

    if (lane >= 4 && s < Smax) sal[s] = a;
    __syncthreads();
    if (tid == 0) {
        const int s2 = 2 * ylen[b];
        const float x = sal[s2], y = sal[s2 - 1];
        const float m = fmaxf(x, y), d = fminf(x, y) - m;
        g_ll[b] = -(m + lg2(1.f + ex2(d))) * LN2;
        __threadfence();
        const int done = atomicAdd(&g_ctr, 1);
        if (done == Bn - 1) {
            float acc = 0.f;
#pragma unroll
            for (int i = 0; i < Bn; i++) acc += g_ll[i];
            out[0] = acc / (float)Bn;
        }
    }
}

// ----------------------------------------------------------------
extern "C" void kernel_launch(void* const* d_in, const int* in_sizes, int n_in,
                              void* d_out, int out_size) {
    const float* hs   = (const float*)d_in[0];
    const int*   hlen = (const int*)d_in[1];
    const int*   ys   = (const int*)d_in[2];
    const int*   ylen = (const int*)d_in[3];
    const float* Wm   = (const float*)d_in[4];
    const float* bias = (const float*)d_in[5];
    float* out = (float*)d_out;

    static bool attrs_set = false;
    if (!attrs_set) {
        cudaFuncSetAttribute(gemm_mma_kernel, cudaFuncAttributeMaxDynamicSharedMemorySize, GEMM_SMEM);
        cudaFuncSetAttribute(ctc_dp_kernel, cudaFuncAttributeMaxDynamicSharedMemorySize, Tn * Jn * 4);
        attrs_set = true;
    }

    prep_kernel<<<6161, 256>>>(hs, Wm, ys);
    gemm_mma_kernel<<<dim3(Vn / 128, Mn / 128), 256, GEMM_SMEM>>>(ys, bias);
    lse_emit_kernel<<<Mn / 8, 256>>>();
    ctc_dp_kernel<<<Bn, 160, Tn * Jn * 4>>>(ys, hlen, ylen, out);
}

// round 16
// speedup vs baseline: 1.3612x; 1.0004x over previous
#include <cuda_runtime.h>
#include <cuda_bf16.h>
#include <cuda_fp8.h>
#include <math.h>
#include <stdint.h>

// ---------------------------------------------------------------- shapes
constexpr int Bn = 16, Tn = 512, Hn = 512, Vn = 4096, Ln = 64, Jn = 66;
constexpr int Mn = Bn * Tn;
constexpr int Smax = 2 * Ln + 1;
constexpr float NEGF = -1e30f;
constexpr float LOG2E = 1.4426950408889634f;
constexpr float LN2 = 0.6931471805599453f;
constexpr float WSCALE = 16.0f;
constexpr float INV_WSCALE = 1.0f / 16.0f;

// ---------------------------------------------------------------- scratch
__device__ uint8_t g_A8[(size_t)Mn * Hn];
__device__ uint8_t g_B8[(size_t)Vn * Hn];
__device__ float2  g_part[(size_t)Mn * 32];   // 1 partial per CTA per row (2 MB)
__device__ float   g_gath[(size_t)Mn * Jn];
__device__ float   g_emit[(size_t)Mn * Jn];
__device__ int     g_rep[Bn * Jn];
__device__ float   g_ll[Bn];
__device__ int     g_ctr;

// ---------------------------------------------------------------- helpers
__device__ __forceinline__ uint32_t smem_u32(const void* p) {
    uint32_t a;
    asm("{ .reg .u64 t; cvta.to.shared.u64 t, %1; cvt.u32.u64 %0, t; }" : "=r"(a) : "l"(p));
    return a;
}
__device__ __forceinline__ void ldm_x4(uint32_t* r, uint32_t addr) {
    asm volatile("ldmatrix.sync.aligned.m8n8.x4.shared.b16 {%0,%1,%2,%3}, [%4];"
                 : "=r"(r[0]), "=r"(r[1]), "=r"(r[2]), "=r"(r[3]) : "r"(addr));
}
__device__ __forceinline__ void ldm_x2(uint32_t* r, uint32_t addr) {
    asm volatile("ldmatrix.sync.aligned.m8n8.x2.shared.b16 {%0,%1}, [%2];"
                 : "=r"(r[0]), "=r"(r[1]) : "r"(addr));
}
__device__ __forceinline__ void mma_fp8(float* d, const uint32_t* a, const uint32_t* b) {
    asm volatile("mma.sync.aligned.m16n8k32.row.col.f32.e4m3.e4m3.f32 "
                 "{%0,%1,%2,%3}, {%4,%5,%6,%7}, {%8,%9}, {%0,%1,%2,%3};"
                 : "+f"(d[0]), "+f"(d[1]), "+f"(d[2]), "+f"(d[3])
                 : "r"(a[0]), "r"(a[1]), "r"(a[2]), "r"(a[3]), "r"(b[0]), "r"(b[1]));
}
__device__ __forceinline__ float ex2(float x) {
    float r; asm("ex2.approx.ftz.f32 %0, %1;" : "=f"(r) : "f"(x)); return r;
}
__device__ __forceinline__ float lg2(float x) {
    float r; asm("lg2.approx.f32 %0, %1;" : "=f"(r) : "f"(x)); return r;
}
__device__ __forceinline__ uint16_t f2_to_e4m3x2(float x, float y) {
    return (uint16_t)__nv_cvt_float2_to_fp8x2(make_float2(x, y), __NV_SATFINITE, __NV_E4M3);
}
#define CP_ASYNC16(dst, src) \
    asm volatile("cp.async.cg.shared.global [%0], [%1], 16;" :: "r"(dst), "l"(src) : "memory")
#define CP_COMMIT() asm volatile("cp.async.commit_group;" ::: "memory")
#define CP_WAIT2()  asm volatile("cp.async.wait_group 2;" ::: "memory")

// ---------------------------------------------------------------- fused preprocessing (coalesced)
// blocks [0,2048): convA (8 floats/thread, 16B stores)
// blocks [2048,2560): convB tile 128k x 32v, 16B fp8 stores
// blocks [2560,2576): rep tables ; 2576: counter reset
__global__ __launch_bounds__(256) void prep_kernel(const float* __restrict__ hs,
                                                   const float* __restrict__ W,
                                                   const int* __restrict__ ys) {
    const int bid = blockIdx.x, tid = threadIdx.x;
    if (bid < 2048) {
        size_t i = (size_t)bid * 256 + tid;   // unit: 8 floats
        float4 v0 = ((const float4*)hs)[i * 2];
        float4 v1 = ((const float4*)hs)[i * 2 + 1];
        uint4 u;
        u.x = (uint32_t)f2_to_e4m3x2(v0.x, v0.y) | ((uint32_t)f2_to_e4m3x2(v0.z, v0.w) << 16);
        u.y = (uint32_t)f2_to_e4m3x2(v1.x, v1.y) | ((uint32_t)f2_to_e4m3x2(v1.z, v1.w) << 16);
        // note: 8 consecutive floats -> 8 consecutive bytes; pack two uint32 halves
        // into first 8 bytes of a uint2-equivalent; use uint2 store (8B) x1
        uint2 w8;
        w8.x = u.x;
        w8.y = u.y;
        ((uint2*)g_A8)[i] = w8;
    } else if (bid < 2560) {
        // convB: W [Hn, Vn] fp32 -> g_B8 [Vn, Hn] fp8(x16). Tile: 128 k x 32 v.
        __shared__ float tile[128][33];
        const int vb = bid - 2048;
        const int v0 = (vb & 127) * 32;      // 128 v-blocks
        const int k0 = (vb >> 7) * 128;      // 4 k-blocks
        const int tx = tid & 31, ty = tid >> 5;   // 32 x 8
#pragma unroll
        for (int i = 0; i < 16; i++)
            tile[ty + 8 * i][tx] = W[(size_t)(k0 + ty + 8 * i) * Vn + v0 + tx];
        __syncthreads();
        // write: 32 v-rows x 128 k-bytes; thread -> (vrow = tid>>3, 16 bytes at (tid&7)*16)
        const int vr = tid >> 3, kc = (tid & 7) * 16;
        uint8_t by[16];
#pragma unroll
        for (int j = 0; j < 16; j++) {
            __nv_fp8_e4m3 q(tile[kc + j][vr] * WSCALE);
            by[j] = *(uint8_t*)&q;
        }
        *(uint4*)(g_B8 + (size_t)(v0 + vr) * Hn + k0 + kc) = *(uint4*)by;
    } else if (bid < 2576) {
        const int b = bid - 2560;
        const int j = tid;
        if (j < 65) {
            const int vid = (j == 0) ? 0 : ys[b * Ln + j - 1];
            int r = j;
            for (int q = 0; q < j; q++) {
                const int vq = (q == 0) ? 0 : ys[b * Ln + q - 1];
                if (vq == vid) { r = q; break; }
            }
            g_rep[b * Jn + j] = r;
        }
    } else {
        if (tid == 0) g_ctr = 0;
    }
}

// ---------------------------------------------------------------- FP8 MMA GEMM (R15 exact)
constexpr int STAGES = 4;
constexpr int STAGE_BYTES = 16384;
constexpr int GEMM_SMEM = STAGES * STAGE_BYTES;

__global__ __launch_bounds__(256, 2) void gemm_mma_kernel(const int* __restrict__ ys,
                                                          const float* __restrict__ bias) {
    extern __shared__ __align__(1024) char sm[];
    __shared__ float sbias[128];
    __shared__ int stable[128];
    __shared__ float2 sred[4][128];

    const int tid = threadIdx.x, w = tid >> 5, lane = tid & 31;
    const int bn = blockIdx.x * 128, bm = blockIdx.y * 128;
    const int b = blockIdx.y >> 2;

    if (tid < 128) { sbias[tid] = bias[bn + tid]; stable[tid] = -1; }
    __syncthreads();
    if (tid == 0) {
        for (int j = 0; j < 65; j++) {
            const int vid = (j == 0) ? 0 : ys[b * Ln + j - 1];
            const int idx = vid - bn;
            if (idx >= 0 && idx < 128 && stable[idx] < 0) stable[idx] = j;
        }
    }

    const int row = tid >> 1, kp = tid & 1;
    const uint8_t* gA = g_A8 + (size_t)(bm + row) * Hn + kp * 16;
    const uint8_t* gB = g_B8 + (size_t)(bn + row) * Hn + kp * 16;
    const uint32_t smb = smem_u32(sm);
    const uint32_t stsA = smb + (uint32_t)(kp * 2) * 2048 + (uint32_t)row * 16;

    const int wm = w >> 2, wn = w & 3;
    const uint32_t aBase = smb + (uint32_t)(wm * 64 + (lane & 15)) * 16 + (uint32_t)(lane >> 4) * 2048;
    const uint32_t bBase = smb + 8192 + (uint32_t)(wn * 32 + (lane & 7)) * 16 + (uint32_t)((lane >> 3) & 1) * 2048;

    float acc[4][4][4];
#pragma unroll
    for (int mi = 0; mi < 4; mi++)
#pragma unroll
        for (int ni = 0; ni < 4; ni++)
#pragma unroll
            for (int e = 0; e < 4; e++) acc[mi][ni][e] = 0.f;

    const int NC = Hn / 64;

#define ISSUE_STAGE(slot, c)                                                   \
    do {                                                                       \
        const uint32_t so = (uint32_t)(slot) * STAGE_BYTES;                    \
        _Pragma("unroll")                                                      \
        for (int i = 0; i < 2; i++) {                                          \
            CP_ASYNC16(stsA + so + i * 2048, gA + (c) * 64 + i * 32);          \
            CP_ASYNC16(stsA + so + 8192 + i * 2048, gB + (c) * 64 + i * 32);   \
        }                                                                      \
    } while (0)

#pragma unroll
    for (int c = 0; c < 3; c++) { ISSUE_STAGE(c, c); CP_COMMIT(); }

    for (int c = 0; c < NC; c++) {
        CP_WAIT2();
        __syncthreads();
        if (c + 3 < NC) ISSUE_STAGE((c + 3) & (STAGES - 1), c + 3);
        CP_COMMIT();

        const uint32_t so = (uint32_t)(c & (STAGES - 1)) * STAGE_BYTES;
#pragma unroll
        for (int kk = 0; kk < 2; kk++) {
            uint32_t aF[4][4], bF[4][2];
#pragma unroll
            for (int mi = 0; mi < 4; mi++)
                ldm_x4(aF[mi], aBase + so + kk * 4096 + mi * 256);
#pragma unroll
            for (int ni = 0; ni < 4; ni++)
                ldm_x2(bF[ni], bBase + so + kk * 4096 + ni * 128);
#pragma unroll
            for (int mi = 0; mi < 4; mi++)
#pragma unroll
                for (int ni = 0; ni < 4; ni++)
                    mma_fp8(acc[mi][ni], aF[mi], bF[ni]);
        }
    }

    // ---- fused epilogue: rescale + bias, per-warp partials -> smem, label gather
    const int tq = lane >> 2, lq = lane & 3;
#pragma unroll
    for (int mi = 0; mi < 4; mi++) {
#pragma unroll
        for (int h = 0; h < 2; h++) {
            const int rloc = wm * 64 + mi * 16 + h * 8 + tq;
            const size_t grow = (size_t)(bm + rloc);
            float v[8];
            float mx = -3.4e38f;
#pragma unroll
            for (int ni = 0; ni < 4; ni++)
#pragma unroll
                for (int e = 0; e < 2; e++) {
                    float f = acc[mi][ni][h * 2 + e] * INV_WSCALE + sbias[wn * 32 + ni * 8 + lq * 2 + e];
                    v[ni * 2 + e] = f;
                    mx = fmaxf(mx, f);
                }
            float sum = 0.f;
#pragma unroll
            for (int i = 0; i < 8; i++) sum += __expf(v[i] - mx);
#pragma unroll
            for (int o = 1; o <= 2; o <<= 1) {
                float mo = __shfl_xor_sync(0xffffffffu, mx, o);
                float so2 = __shfl_xor_sync(0xffffffffu, sum, o);
                float m2 = fmaxf(mx, mo);
                sum = sum * __expf(mx - m2) + so2 * __expf(mo - m2);
                mx = m2;
            }
            if (lq == 0) sred[wn][rloc] = make_float2(mx, sum);
#pragma unroll
            for (int ni = 0; ni < 4; ni++)
#pragma unroll
                for (int e = 0; e < 2; e++) {
                    const int cidx = wn * 32 + ni * 8 + lq * 2 + e;
                    const int slot = stable[cidx];
                    if (slot >= 0) g_gath[grow * Jn + slot] = v[ni * 2 + e];
                }
        }
    }
    // ---- cross-warp reduce: 4 partials -> 1 per row
    __syncthreads();
    if (tid < 128) {
        float2 p0 = sred[0][tid], p1 = sred[1][tid], p2 = sred[2][tid], p3 = sred[3][tid];
        float m = fmaxf(fmaxf(p0.x, p1.x), fmaxf(p2.x, p3.x));
        float s = p0.y * __expf(p0.x - m) + p1.y * __expf(p1.x - m)
                + p2.y * __expf(p2.x - m) + p3.y * __expf(p3.x - m);
        g_part[(size_t)(bm + tid) * 32 + blockIdx.x] = make_float2(m, s);
    }
}

// ---------------------------------------------------------------- LSE reduce (32 partials/row) + emit
__global__ __launch_bounds__(256) void lse_emit_kernel() {
    const int warp = threadIdx.x >> 5, lane = threadIdx.x & 31;
    const size_t row = (size_t)blockIdx.x * 8 + warp;
    const int b = (int)(row >> 9);
    float2 p = g_part[row * 32 + lane];
    float m = p.x;
#pragma unroll
    for (int o = 16; o > 0; o >>= 1) m = fmaxf(m, __shfl_xor_sync(0xffffffffu, m, o));
    float s = p.y * __expf(p.x - m);
#pragma unroll
    for (int o = 16; o > 0; o >>= 1) s += __shfl_xor_sync(0xffffffffu, s, o);
    const float lse = m + __logf(s);
#pragma unroll
    for (int j = lane; j < 65; j += 32)
        g_emit[row * Jn + j] = (g_gath[row * Jn + g_rep[b * Jn + j]] - lse) * LOG2E;
}

// ---------------------------------------------------------------- CTC DP: halo-4 wavefront (R11/R6 exact)
__global__ __launch_bounds__(160) void ctc_dp_kernel(const int* __restrict__ ys,
                                                     const int* __restrict__ hlen,
                                                     const int* __restrict__ ylen,
                                                     float* __restrict__ out) {
    extern __shared__ float sem[];
    __shared__ float sbuf[2][20];
    __shared__ float sal[Smax + 12];

    const int b = blockIdx.x, tid = threadIdx.x;
    const int w = tid >> 5, lane = tid & 31;
    const int s = w * 28 + lane - 4;
    const int inlen = hlen[b];

    {
        const float2* src = (const float2*)(g_emit + (size_t)b * Tn * Jn);
        float2* dst = (float2*)sem;
        const int n2 = inlen * (Jn / 2);
        for (int i = tid; i < n2; i += 160) dst[i] = src[i];
    }

    int jj = 0;
    bool skipv = false;
    if (s >= 0 && s < Smax && (s & 1)) {
        const int li = (s - 1) >> 1;
        jj = li + 1;
        const int lab = ys[b * Ln + li];
        if (s >= 3) skipv = (lab != 0) && (lab != ys[b * Ln + li - 1]);
    }
    __syncthreads();

    float a = (s == 0) ? sem[0] : (s == 1) ? sem[1] : NEGF;
    int pb = 0;
    if (lane >= 28) sbuf[0][w * 4 + lane - 28] = a;
    __syncthreads();

    for (int t = 1; t < inlen; t += 2) {
        if (lane < 4) a = (w > 0) ? sbuf[pb][(w - 1) * 4 + lane] : NEGF;
        {
            const float e = sem[t * Jn + jj];
            const float up1 = __shfl_up_sync(0xffffffffu, a, 1);
            const float up2 = __shfl_up_sync(0xffffffffu, a, 2);
            const float am2 = skipv ? up2 : NEGF;
            const float m = fmaxf(fmaxf(a, up1), am2);
            a = m + lg2(ex2(a - m) + ex2(up1 - m) + ex2(am2 - m)) + e;
        }
        if (t + 1 < inlen) {
            const float e = sem[(t + 1) * Jn + jj];
            const float up1 = __shfl_up_sync(0xffffffffu, a, 1);
            const float up2 = __shfl_up_sync(0xffffffffu, a, 2);
            const float am2 = skipv ? up2 : NEGF;
            const float m = fmaxf(fmaxf(a, up1), am2);
            a = m + lg2(ex2(a - m) + ex2(up1 - m) + ex2(am2 - m)) + e;
        }
        pb ^= 1;
        if (lane >= 28) sbuf[pb][w * 4 + lane - 28] = a;
        __syncthreads();
    }

    if (lane >= 4 && s < Smax) sal[s] = a;
    __syncthreads();
    if (tid == 0) {
        const int s2 = 2 * ylen[b];
        const float x = sal[s2], y = sal[s2 - 1];
        const float m = fmaxf(x, y), d = fminf(x, y) - m;
        g_ll[b] = -(m + lg2(1.f + ex2(d))) * LN2;
        __threadfence();
        const int done = atomicAdd(&g_ctr, 1);
        if (done == Bn - 1) {
            float acc = 0.f;
#pragma unroll
            for (int i = 0; i < Bn; i++) acc += g_ll[i];
            out[0] = acc / (float)Bn;
        }
    }
}

// ----------------------------------------------------------------
extern "C" void kernel_launch(void* const* d_in, const int* in_sizes, int n_in,
                              void* d_out, int out_size) {
    const float* hs   = (const float*)d_in[0];
    const int*   hlen = (const int*)d_in[1];
    const int*   ys   = (const int*)d_in[2];
    const int*   ylen = (const int*)d_in[3];
    const float* Wm   = (const float*)d_in[4];
    const float* bias = (const float*)d_in[5];
    float* out = (float*)d_out;

    static bool attrs_set = false;
    if (!attrs_set) {
        cudaFuncSetAttribute(gemm_mma_kernel, cudaFuncAttributeMaxDynamicSharedMemorySize, GEMM_SMEM);
        cudaFuncSetAttribute(ctc_dp_kernel, cudaFuncAttributeMaxDynamicSharedMemorySize, Tn * Jn * 4);
        attrs_set = true;
    }

    prep_kernel<<<2577, 256>>>(hs, Wm, ys);
    gemm_mma_kernel<<<dim3(Vn / 128, Mn / 128), 256, GEMM_SMEM>>>(ys, bias);
    lse_emit_kernel<<<Mn / 8, 256>>>();
    ctc_dp_kernel<<<Bn, 160, Tn * Jn * 4>>>(ys, hlen, ylen, out);
}

// round 17
// speedup vs baseline: 1.4837x; 1.0900x over previous
#include <cuda_runtime.h>
#include <cuda_bf16.h>
#include <cuda_fp8.h>
#include <math.h>
#include <stdint.h>

// ---------------------------------------------------------------- shapes
constexpr int Bn = 16, Tn = 512, Hn = 512, Vn = 4096, Ln = 64, Jn = 66;
constexpr int Mn = Bn * Tn;
constexpr int Smax = 2 * Ln + 1;
constexpr float NEGF = -1e30f;
constexpr float LOG2E = 1.4426950408889634f;
constexpr float LN2 = 0.6931471805599453f;
constexpr float WSCALE = 16.0f;
constexpr float INV_WSCALE = 1.0f / 16.0f;

// ---------------------------------------------------------------- scratch
__device__ uint8_t g_A8[(size_t)Mn * Hn];
__device__ uint8_t g_B8[(size_t)Vn * Hn];
__device__ float2  g_part[(size_t)Mn * 32];
__device__ float   g_gath[(size_t)Mn * Jn];
__device__ float   g_emit[(size_t)Mn * Jn];
__device__ int     g_rep[Bn * Jn];
__device__ float   g_ll[Bn];
__device__ int     g_ctr;

// ---------------------------------------------------------------- helpers
__device__ __forceinline__ uint32_t smem_u32(const void* p) {
    uint32_t a;
    asm("{ .reg .u64 t; cvta.to.shared.u64 t, %1; cvt.u32.u64 %0, t; }" : "=r"(a) : "l"(p));
    return a;
}
__device__ __forceinline__ void ldm_x4(uint32_t* r, uint32_t addr) {
    asm volatile("ldmatrix.sync.aligned.m8n8.x4.shared.b16 {%0,%1,%2,%3}, [%4];"
                 : "=r"(r[0]), "=r"(r[1]), "=r"(r[2]), "=r"(r[3]) : "r"(addr));
}
__device__ __forceinline__ void ldm_x2(uint32_t* r, uint32_t addr) {
    asm volatile("ldmatrix.sync.aligned.m8n8.x2.shared.b16 {%0,%1}, [%2];"
                 : "=r"(r[0]), "=r"(r[1]) : "r"(addr));
}
__device__ __forceinline__ void mma_fp8(float* d, const uint32_t* a, const uint32_t* b) {
    asm volatile("mma.sync.aligned.m16n8k32.row.col.f32.e4m3.e4m3.f32 "
                 "{%0,%1,%2,%3}, {%4,%5,%6,%7}, {%8,%9}, {%0,%1,%2,%3};"
                 : "+f"(d[0]), "+f"(d[1]), "+f"(d[2]), "+f"(d[3])
                 : "r"(a[0]), "r"(a[1]), "r"(a[2]), "r"(a[3]), "r"(b[0]), "r"(b[1]));
}
__device__ __forceinline__ float ex2(float x) {
    float r; asm("ex2.approx.ftz.f32 %0, %1;" : "=f"(r) : "f"(x)); return r;
}
__device__ __forceinline__ float lg2(float x) {
    float r; asm("lg2.approx.f32 %0, %1;" : "=f"(r) : "f"(x)); return r;
}
__device__ __forceinline__ uint16_t f2_to_e4m3x2(float x, float y) {
    return (uint16_t)__nv_cvt_float2_to_fp8x2(make_float2(x, y), __NV_SATFINITE, __NV_E4M3);
}
#define CP_ASYNC16(dst, src) \
    asm volatile("cp.async.cg.shared.global [%0], [%1], 16;" :: "r"(dst), "l"(src) : "memory")
#define CP_COMMIT() asm volatile("cp.async.commit_group;" ::: "memory")
#define CP_WAIT2()  asm volatile("cp.async.wait_group 2;" ::: "memory")

// ---------------------------------------------------------------- fused preprocessing (coalesced)
__global__ __launch_bounds__(256) void prep_kernel(const float* __restrict__ hs,
                                                   const float* __restrict__ W,
                                                   const int* __restrict__ ys) {
    const int bid = blockIdx.x, tid = threadIdx.x;
    if (bid < 2048) {
        size_t i = (size_t)bid * 256 + tid;   // unit: 8 floats
        float4 v0 = ((const float4*)hs)[i * 2];
        float4 v1 = ((const float4*)hs)[i * 2 + 1];
        uint2 w8;
        w8.x = (uint32_t)f2_to_e4m3x2(v0.x, v0.y) | ((uint32_t)f2_to_e4m3x2(v0.z, v0.w) << 16);
        w8.y = (uint32_t)f2_to_e4m3x2(v1.x, v1.y) | ((uint32_t)f2_to_e4m3x2(v1.z, v1.w) << 16);
        ((uint2*)g_A8)[i] = w8;
    } else if (bid < 2560) {
        __shared__ float tile[128][33];
        const int vb = bid - 2048;
        const int v0 = (vb & 127) * 32;
        const int k0 = (vb >> 7) * 128;
        const int tx = tid & 31, ty = tid >> 5;
#pragma unroll
        for (int i = 0; i < 16; i++)
            tile[ty + 8 * i][tx] = W[(size_t)(k0 + ty + 8 * i) * Vn + v0 + tx];
        __syncthreads();
        const int vr = tid >> 3, kc = (tid & 7) * 16;
        uint8_t by[16];
#pragma unroll
        for (int j = 0; j < 16; j++) {
            __nv_fp8_e4m3 q(tile[kc + j][vr] * WSCALE);
            by[j] = *(uint8_t*)&q;
        }
        *(uint4*)(g_B8 + (size_t)(v0 + vr) * Hn + k0 + kc) = *(uint4*)by;
    } else if (bid < 2576) {
        const int b = bid - 2560;
        const int j = tid;
        if (j < 65) {
            const int vid = (j == 0) ? 0 : ys[b * Ln + j - 1];
            int r = j;
            for (int q = 0; q < j; q++) {
                const int vq = (q == 0) ? 0 : ys[b * Ln + q - 1];
                if (vq == vid) { r = q; break; }
            }
            g_rep[b * Jn + j] = r;
        }
    } else {
        if (tid == 0) g_ctr = 0;
    }
}

// ---------------------------------------------------------------- FP8 MMA GEMM (R15 exact) + dead-row gate
constexpr int STAGES = 4;
constexpr int STAGE_BYTES = 16384;
constexpr int GEMM_SMEM = STAGES * STAGE_BYTES;

__global__ __launch_bounds__(256, 2) void gemm_mma_kernel(const int* __restrict__ ys,
                                                          const float* __restrict__ bias,
                                                          const int* __restrict__ hlen) {
    extern __shared__ __align__(1024) char sm[];
    __shared__ float sbias[128];
    __shared__ int stable[128];
    __shared__ float2 sred[4][128];

    const int tid = threadIdx.x, w = tid >> 5, lane = tid & 31;
    const int bn = blockIdx.x * 128, bm = blockIdx.y * 128;
    const int b = blockIdx.y >> 2;

    // dead-row gate: this CTA's rows are t in [(blockIdx.y&3)*128, +128) of batch b.
    // If all are >= hs_lens[b], no consumer ever reads them.
    if (((blockIdx.y & 3) << 7) >= hlen[b]) return;

    if (tid < 128) { sbias[tid] = bias[bn + tid]; stable[tid] = -1; }
    __syncthreads();
    if (tid == 0) {
        for (int j = 0; j < 65; j++) {
            const int vid = (j == 0) ? 0 : ys[b * Ln + j - 1];
            const int idx = vid - bn;
            if (idx >= 0 && idx < 128 && stable[idx] < 0) stable[idx] = j;
        }
    }

    const int row = tid >> 1, kp = tid & 1;
    const uint8_t* gA = g_A8 + (size_t)(bm + row) * Hn + kp * 16;
    const uint8_t* gB = g_B8 + (size_t)(bn + row) * Hn + kp * 16;
    const uint32_t smb = smem_u32(sm);
    const uint32_t stsA = smb + (uint32_t)(kp * 2) * 2048 + (uint32_t)row * 16;

    const int wm = w >> 2, wn = w & 3;
    const uint32_t aBase = smb + (uint32_t)(wm * 64 + (lane & 15)) * 16 + (uint32_t)(lane >> 4) * 2048;
    const uint32_t bBase = smb + 8192 + (uint32_t)(wn * 32 + (lane & 7)) * 16 + (uint32_t)((lane >> 3) & 1) * 2048;

    float acc[4][4][4];
#pragma unroll
    for (int mi = 0; mi < 4; mi++)
#pragma unroll
        for (int ni = 0; ni < 4; ni++)
#pragma unroll
            for (int e = 0; e < 4; e++) acc[mi][ni][e] = 0.f;

    const int NC = Hn / 64;

#define ISSUE_STAGE(slot, c)                                                   \
    do {                                                                       \
        const uint32_t so = (uint32_t)(slot) * STAGE_BYTES;                    \
        _Pragma("unroll")                                                      \
        for (int i = 0; i < 2; i++) {                                          \
            CP_ASYNC16(stsA + so + i * 2048, gA + (c) * 64 + i * 32);          \
            CP_ASYNC16(stsA + so + 8192 + i * 2048, gB + (c) * 64 + i * 32);   \
        }                                                                      \
    } while (0)

#pragma unroll
    for (int c = 0; c < 3; c++) { ISSUE_STAGE(c, c); CP_COMMIT(); }

    for (int c = 0; c < NC; c++) {
        CP_WAIT2();
        __syncthreads();
        if (c + 3 < NC) ISSUE_STAGE((c + 3) & (STAGES - 1), c + 3);
        CP_COMMIT();

        const uint32_t so = (uint32_t)(c & (STAGES - 1)) * STAGE_BYTES;
#pragma unroll
        for (int kk = 0; kk < 2; kk++) {
            uint32_t aF[4][4], bF[4][2];
#pragma unroll
            for (int mi = 0; mi < 4; mi++)
                ldm_x4(aF[mi], aBase + so + kk * 4096 + mi * 256);
#pragma unroll
            for (int ni = 0; ni < 4; ni++)
                ldm_x2(bF[ni], bBase + so + kk * 4096 + ni * 128);
#pragma unroll
            for (int mi = 0; mi < 4; mi++)
#pragma unroll
                for (int ni = 0; ni < 4; ni++)
                    mma_fp8(acc[mi][ni], aF[mi], bF[ni]);
        }
    }

    // ---- fused epilogue: rescale + bias, per-warp partials -> smem, label gather
    const int tq = lane >> 2, lq = lane & 3;
#pragma unroll
    for (int mi = 0; mi < 4; mi++) {
#pragma unroll
        for (int h = 0; h < 2; h++) {
            const int rloc = wm * 64 + mi * 16 + h * 8 + tq;
            const size_t grow = (size_t)(bm + rloc);
            float v[8];
            float mx = -3.4e38f;
#pragma unroll
            for (int ni = 0; ni < 4; ni++)
#pragma unroll
                for (int e = 0; e < 2; e++) {
                    float f = acc[mi][ni][h * 2 + e] * INV_WSCALE + sbias[wn * 32 + ni * 8 + lq * 2 + e];
                    v[ni * 2 + e] = f;
                    mx = fmaxf(mx, f);
                }
            float sum = 0.f;
#pragma unroll
            for (int i = 0; i < 8; i++) sum += __expf(v[i] - mx);
#pragma unroll
            for (int o = 1; o <= 2; o <<= 1) {
                float mo = __shfl_xor_sync(0xffffffffu, mx, o);
                float so2 = __shfl_xor_sync(0xffffffffu, sum, o);
                float m2 = fmaxf(mx, mo);
                sum = sum * __expf(mx - m2) + so2 * __expf(mo - m2);
                mx = m2;
            }
            if (lq == 0) sred[wn][rloc] = make_float2(mx, sum);
#pragma unroll
            for (int ni = 0; ni < 4; ni++)
#pragma unroll
                for (int e = 0; e < 2; e++) {
                    const int cidx = wn * 32 + ni * 8 + lq * 2 + e;
                    const int slot = stable[cidx];
                    if (slot >= 0) g_gath[grow * Jn + slot] = v[ni * 2 + e];
                }
        }
    }
    // ---- cross-warp reduce: 4 partials -> 1 per row
    __syncthreads();
    if (tid < 128) {
        float2 p0 = sred[0][tid], p1 = sred[1][tid], p2 = sred[2][tid], p3 = sred[3][tid];
        float m = fmaxf(fmaxf(p0.x, p1.x), fmaxf(p2.x, p3.x));
        float s = p0.y * __expf(p0.x - m) + p1.y * __expf(p1.x - m)
                + p2.y * __expf(p2.x - m) + p3.y * __expf(p3.x - m);
        g_part[(size_t)(bm + tid) * 32 + blockIdx.x] = make_float2(m, s);
    }
}

// ---------------------------------------------------------------- LSE reduce (32 partials/row) + emit, gated
__global__ __launch_bounds__(256) void lse_emit_kernel(const int* __restrict__ hlen) {
    const int warp = threadIdx.x >> 5, lane = threadIdx.x & 31;
    const size_t row = (size_t)blockIdx.x * 8 + warp;
    const int b = (int)(row >> 9);
    if ((int)(row & 511) >= hlen[b]) return;   // dead row: never read by DP
    float2 p = g_part[row * 32 + lane];
    float m = p.x;
#pragma unroll
    for (int o = 16; o > 0; o >>= 1) m = fmaxf(m, __shfl_xor_sync(0xffffffffu, m, o));
    float s = p.y * __expf(p.x - m);
#pragma unroll
    for (int o = 16; o > 0; o >>= 1) s += __shfl_xor_sync(0xffffffffu, s, o);
    const float lse = m + __logf(s);
#pragma unroll
    for (int j = lane; j < 65; j += 32)
        g_emit[row * Jn + j] = (g_gath[row * Jn + g_rep[b * Jn + j]] - lse) * LOG2E;
}

// ---------------------------------------------------------------- CTC DP: halo-4 wavefront (R11/R6 exact)
__global__ __launch_bounds__(160) void ctc_dp_kernel(const int* __restrict__ ys,
                                                     const int* __restrict__ hlen,
                                                     const int* __restrict__ ylen,
                                                     float* __restrict__ out) {
    extern __shared__ float sem[];
    __shared__ float sbuf[2][20];
    __shared__ float sal[Smax + 12];

    const int b = blockIdx.x, tid = threadIdx.x;
    const int w = tid >> 5, lane = tid & 31;
    const int s = w * 28 + lane - 4;
    const int inlen = hlen[b];

    {
        const float2* src = (const float2*)(g_emit + (size_t)b * Tn * Jn);
        float2* dst = (float2*)sem;
        const int n2 = inlen * (Jn / 2);
        for (int i = tid; i < n2; i += 160) dst[i] = src[i];
    }

    int jj = 0;
    bool skipv = false;
    if (s >= 0 && s < Smax && (s & 1)) {
        const int li = (s - 1) >> 1;
        jj = li + 1;
        const int lab = ys[b * Ln + li];
        if (s >= 3) skipv = (lab != 0) && (lab != ys[b * Ln + li - 1]);
    }
    __syncthreads();

    float a = (s == 0) ? sem[0] : (s == 1) ? sem[1] : NEGF;
    int pb = 0;
    if (lane >= 28) sbuf[0][w * 4 + lane - 28] = a;
    __syncthreads();

    for (int t = 1; t < inlen; t += 2) {
        if (lane < 4) a = (w > 0) ? sbuf[pb][(w - 1) * 4 + lane] : NEGF;
        {
            const float e = sem[t * Jn + jj];
            const float up1 = __shfl_up_sync(0xffffffffu, a, 1);
            const float up2 = __shfl_up_sync(0xffffffffu, a, 2);
            const float am2 = skipv ? up2 : NEGF;
            const float m = fmaxf(fmaxf(a, up1), am2);
            a = m + lg2(ex2(a - m) + ex2(up1 - m) + ex2(am2 - m)) + e;
        }
        if (t + 1 < inlen) {
            const float e = sem[(t + 1) * Jn + jj];
            const float up1 = __shfl_up_sync(0xffffffffu, a, 1);
            const float up2 = __shfl_up_sync(0xffffffffu, a, 2);
            const float am2 = skipv ? up2 : NEGF;
            const float m = fmaxf(fmaxf(a, up1), am2);
            a = m + lg2(ex2(a - m) + ex2(up1 - m) + ex2(am2 - m)) + e;
        }
        pb ^= 1;
        if (lane >= 28) sbuf[pb][w * 4 + lane - 28] = a;
        __syncthreads();
    }

    if (lane >= 4 && s < Smax) sal[s] = a;
    __syncthreads();
    if (tid == 0) {
        const int s2 = 2 * ylen[b];
        const float x = sal[s2], y = sal[s2 - 1];
        const float m = fmaxf(x, y), d = fminf(x, y) - m;
        g_ll[b] = -(m + lg2(1.f + ex2(d))) * LN2;
        __threadfence();
        const int done = atomicAdd(&g_ctr, 1);
        if (done == Bn - 1) {
            float acc = 0.f;
#pragma unroll
            for (int i = 0; i < Bn; i++) acc += g_ll[i];
            out[0] = acc / (float)Bn;
        }
    }
}

// ----------------------------------------------------------------
extern "C" void kernel_launch(void* const* d_in, const int* in_sizes, int n_in,
                              void* d_out, int out_size) {
    const float* hs   = (const float*)d_in[0];
    const int*   hlen = (const int*)d_in[1];
    const int*   ys   = (const int*)d_in[2];
    const int*   ylen = (const int*)d_in[3];
    const float* Wm   = (const float*)d_in[4];
    const float* bias = (const float*)d_in[5];
    float* out = (float*)d_out;

    static bool attrs_set = false;
    if (!attrs_set) {
        cudaFuncSetAttribute(gemm_mma_kernel, cudaFuncAttributeMaxDynamicSharedMemorySize, GEMM_SMEM);
        cudaFuncSetAttribute(ctc_dp_kernel, cudaFuncAttributeMaxDynamicSharedMemorySize, Tn * Jn * 4);
        attrs_set = true;
    }

    prep_kernel<<<2577, 256>>>(hs, Wm, ys);
    gemm_mma_kernel<<<dim3(Vn / 128, Mn / 128), 256, GEMM_SMEM>>>(ys, bias, hlen);
    lse_emit_kernel<<<Mn / 8, 256>>>(hlen);
    ctc_dp_kernel<<<Bn, 160, Tn * Jn * 4>>>(ys, hlen, ylen, out);
}